// round 16
// baseline (speedup 1.0000x reference)
#include <cuda_runtime.h>

#define NB 4
#define NQ 128
#define NK 1024
#define HD 256
#define DV 256

// Scratch (device globals — no allocation allowed)
__device__ float g_qp[NB * NQ * HD];      // 512 KB projected queries
__device__ float g_kp[NB * NK * HD];      // 4 MB projected keys
__device__ float g_scores[NB * NQ * NK];  // 2 MB scores -> probs (in place)

__device__ __forceinline__ float tanh_fast(float x) {
    float y;
    asm("tanh.approx.f32 %0, %1;" : "=f"(y) : "f"(x));
    return y;
}

// tf32 hi/lo split (3xTF32 scheme): x ≈ hi + lo with both tf32-representable
__device__ __forceinline__ void tf32_split(float x, float& hi, float& lo) {
    unsigned h, l;
    asm("cvt.rna.tf32.f32 %0, %1;" : "=r"(h) : "f"(x));
    hi = __uint_as_float(h);
    float r = x - hi;
    asm("cvt.rna.tf32.f32 %0, %1;" : "=r"(l) : "f"(r));
    lo = __uint_as_float(l);
}

__device__ __forceinline__ void mma_tf32(float* d, const unsigned* a,
                                         const unsigned* b) {
    asm volatile(
        "mma.sync.aligned.m16n8k8.row.col.f32.tf32.tf32.f32 "
        "{%0,%1,%2,%3}, {%4,%5,%6,%7}, {%8,%9}, {%0,%1,%2,%3};"
        : "+f"(d[0]), "+f"(d[1]), "+f"(d[2]), "+f"(d[3])
        : "r"(a[0]), "r"(a[1]), "r"(a[2]), "r"(a[3]),
          "r"(b[0]), "r"(b[1]));
}

// -------------------------------------------------------------------------
// Fused projections via tensor cores (3xTF32) — R15 winner, unchanged.
// -------------------------------------------------------------------------
__global__ __launch_bounds__(256) void proj_kernel(
    const float* __restrict__ Q, const float* __restrict__ K,
    const float* __restrict__ Wq, const float* __restrict__ Wk,
    const int* __restrict__ valid_lens)
{
    __shared__ float Ah[64][36], Al[64][36];   // X tile hi/lo  [row][d]
    __shared__ float Bh[64][36], Bl[64][36];   // W tile hi/lo  [h][d]

    const int by = blockIdx.y;
    const float* X;
    const float* W;
    float* out;
    int r0;
    if (by < 8) { X = Q; W = Wq; out = g_qp; r0 = by * 64; }
    else {
        const int t = by - 8;              // 0..63 over 4096 key rows
        const int b = t >> 4;
        const int k0l = (t & 15) * 64;
        if (k0l >= valid_lens[b]) return;  // dead keys: never read downstream
        X = K; W = Wk; out = g_kp; r0 = t * 64;
    }

    const int h0 = blockIdx.x * 64;
    const int tid  = threadIdx.x;
    const int lane = tid & 31;
    const int warp = tid >> 5;
    const int wm0 = (warp & 3) * 16;       // warp row strip
    const int wn0 = (warp >> 2) * 32;      // warp col strip
    const int g = lane >> 2;               // 0..7
    const int t4 = lane & 3;               // 0..3

    const int lr = tid >> 2;               // 0..63 (loader row)
    const int lc = (tid & 3) * 8;          // 0,8,16,24 (loader col base)

    float acc[4][4] = {};                  // 4 n-tiles x 4 regs

    for (int d0 = 0; d0 < HD; d0 += 32) {
        float4 xa = *(const float4*)&X[(size_t)(r0 + lr) * HD + d0 + lc];
        float4 xb = *(const float4*)&X[(size_t)(r0 + lr) * HD + d0 + lc + 4];
        float4 wa = *(const float4*)&W[(size_t)(h0 + lr) * HD + d0 + lc];
        float4 wb = *(const float4*)&W[(size_t)(h0 + lr) * HD + d0 + lc + 4];

        float4 xh0, xl0, xh1, xl1, wh0, wl0, wh1, wl1;
        tf32_split(xa.x, xh0.x, xl0.x); tf32_split(xa.y, xh0.y, xl0.y);
        tf32_split(xa.z, xh0.z, xl0.z); tf32_split(xa.w, xh0.w, xl0.w);
        tf32_split(xb.x, xh1.x, xl1.x); tf32_split(xb.y, xh1.y, xl1.y);
        tf32_split(xb.z, xh1.z, xl1.z); tf32_split(xb.w, xh1.w, xl1.w);
        tf32_split(wa.x, wh0.x, wl0.x); tf32_split(wa.y, wh0.y, wl0.y);
        tf32_split(wa.z, wh0.z, wl0.z); tf32_split(wa.w, wh0.w, wl0.w);
        tf32_split(wb.x, wh1.x, wl1.x); tf32_split(wb.y, wh1.y, wl1.y);
        tf32_split(wb.z, wh1.z, wl1.z); tf32_split(wb.w, wh1.w, wl1.w);

        *(float4*)&Ah[lr][lc]     = xh0; *(float4*)&Ah[lr][lc + 4] = xh1;
        *(float4*)&Al[lr][lc]     = xl0; *(float4*)&Al[lr][lc + 4] = xl1;
        *(float4*)&Bh[lr][lc]     = wh0; *(float4*)&Bh[lr][lc + 4] = wh1;
        *(float4*)&Bl[lr][lc]     = wl0; *(float4*)&Bl[lr][lc + 4] = wl1;
        __syncthreads();

        #pragma unroll
        for (int k8 = 0; k8 < 32; k8 += 8) {
            unsigned ah[4], al[4];
            ah[0] = __float_as_uint(Ah[wm0 + g    ][k8 + t4    ]);
            ah[1] = __float_as_uint(Ah[wm0 + g + 8][k8 + t4    ]);
            ah[2] = __float_as_uint(Ah[wm0 + g    ][k8 + t4 + 4]);
            ah[3] = __float_as_uint(Ah[wm0 + g + 8][k8 + t4 + 4]);
            al[0] = __float_as_uint(Al[wm0 + g    ][k8 + t4    ]);
            al[1] = __float_as_uint(Al[wm0 + g + 8][k8 + t4    ]);
            al[2] = __float_as_uint(Al[wm0 + g    ][k8 + t4 + 4]);
            al[3] = __float_as_uint(Al[wm0 + g + 8][k8 + t4 + 4]);

            #pragma unroll
            for (int j = 0; j < 4; j++) {
                const int hrow = wn0 + j * 8 + g;
                unsigned bh[2], bl[2];
                bh[0] = __float_as_uint(Bh[hrow][k8 + t4    ]);
                bh[1] = __float_as_uint(Bh[hrow][k8 + t4 + 4]);
                bl[0] = __float_as_uint(Bl[hrow][k8 + t4    ]);
                bl[1] = __float_as_uint(Bl[hrow][k8 + t4 + 4]);

                mma_tf32(acc[j], ah, bh);   // hi*hi
                mma_tf32(acc[j], ah, bl);   // hi*lo
                mma_tf32(acc[j], al, bh);   // lo*hi
            }
        }
        __syncthreads();
    }

    #pragma unroll
    for (int j = 0; j < 4; j++) {
        const int col = h0 + wn0 + j * 8 + t4 * 2;
        *(float2*)&out[(size_t)(r0 + wm0 + g    ) * HD + col] =
            make_float2(acc[j][0], acc[j][1]);
        *(float2*)&out[(size_t)(r0 + wm0 + g + 8) * HD + col] =
            make_float2(acc[j][2], acc[j][3]);
    }
}

// -------------------------------------------------------------------------
// Scores: s[b,q,k] = sum_h wv[h] * tanh(qp[b,q,h] + kp[b,k,h])
// f32 tanh (MUFU floor). Only k < valid_len[b] computed. Unchanged.
// -------------------------------------------------------------------------
__global__ __launch_bounds__(128) void scores_kernel(
    const float* __restrict__ wv, const int* __restrict__ valid_lens)
{
    const int b  = blockIdx.z;
    const int q0 = blockIdx.y * 8;
    const int k0 = blockIdx.x * 64;
    const int warp = threadIdx.x >> 5;
    const int lane = threadIdx.x & 31;
    const int hbase = lane * 8;

    const int vlen = valid_lens[b];
    const int kw0 = k0 + warp * 16;
    int nit = vlen - kw0;
    if (nit <= 0) return;
    if (nit > 16) nit = 16;

    float qreg[8][8];
    const float* qbase = g_qp + (size_t)(b * NQ + q0) * HD + hbase;
    #pragma unroll
    for (int j = 0; j < 8; j++) {
        float4 a = *(const float4*)(qbase + j * HD);
        float4 c = *(const float4*)(qbase + j * HD + 4);
        qreg[j][0] = a.x; qreg[j][1] = a.y; qreg[j][2] = a.z; qreg[j][3] = a.w;
        qreg[j][4] = c.x; qreg[j][5] = c.y; qreg[j][6] = c.z; qreg[j][7] = c.w;
    }

    float wr[8];
    {
        float4 a = *(const float4*)(wv + hbase);
        float4 c = *(const float4*)(wv + hbase + 4);
        wr[0] = a.x; wr[1] = a.y; wr[2] = a.z; wr[3] = a.w;
        wr[4] = c.x; wr[5] = c.y; wr[6] = c.z; wr[7] = c.w;
    }

    const float* kbase = g_kp + (size_t)b * NK * HD + hbase;

    float4 ka = *(const float4*)(kbase + (size_t)kw0 * HD);
    float4 kc = *(const float4*)(kbase + (size_t)kw0 * HD + 4);

    for (int it = 0; it < nit; it++) {
        float4 na, nc;
        if (it + 1 < nit) {
            const float* np = kbase + (size_t)(kw0 + it + 1) * HD;
            na = *(const float4*)np;
            nc = *(const float4*)(np + 4);
        }

        float kr[8] = {ka.x, ka.y, ka.z, ka.w, kc.x, kc.y, kc.z, kc.w};

        float acc[8];
        #pragma unroll
        for (int j = 0; j < 8; j++) {
            float s = 0.f;
            #pragma unroll
            for (int i = 0; i < 8; i++)
                s += wr[i] * tanh_fast(qreg[j][i] + kr[i]);
            acc[j] = s;
        }

        #pragma unroll
        for (int j = 0; j < 8; j++) {
            float v = acc[j];
            v += __shfl_xor_sync(0xFFFFFFFFu, v, 16);
            v += __shfl_xor_sync(0xFFFFFFFFu, v, 8);
            v += __shfl_xor_sync(0xFFFFFFFFu, v, 4);
            v += __shfl_xor_sync(0xFFFFFFFFu, v, 2);
            v += __shfl_xor_sync(0xFFFFFFFFu, v, 1);
            if (lane == 0)
                g_scores[(size_t)(b * NQ + q0 + j) * NK + kw0 + it] = v;
        }

        ka = na; kc = nc;
    }
}

// -------------------------------------------------------------------------
// Masked softmax over each 1024-long score row, in place. Unchanged.
// -------------------------------------------------------------------------
__global__ __launch_bounds__(256) void softmax_kernel(
    const int* __restrict__ valid_lens, float* __restrict__ out)
{
    __shared__ float red[8];

    const int row = blockIdx.x;             // 0..511
    const int b   = row >> 7;
    const int tid = threadIdx.x;
    const int warp = tid >> 5;
    const int lane = tid & 31;
    const int vlen = valid_lens[b];

    out[(size_t)row * DV + tid] = 0.f;

    float* rp = g_scores + (size_t)row * NK + tid * 4;

    float4 v = *(const float4*)rp;
    const int kb = tid * 4;
    if (kb + 0 >= vlen) v.x = -1e6f;
    if (kb + 1 >= vlen) v.y = -1e6f;
    if (kb + 2 >= vlen) v.z = -1e6f;
    if (kb + 3 >= vlen) v.w = -1e6f;

    float mx = fmaxf(fmaxf(v.x, v.y), fmaxf(v.z, v.w));
    #pragma unroll
    for (int off = 16; off; off >>= 1)
        mx = fmaxf(mx, __shfl_xor_sync(0xFFFFFFFFu, mx, off));
    if (lane == 0) red[warp] = mx;
    __syncthreads();
    if (warp == 0) {
        float m = red[lane & 7];
        #pragma unroll
        for (int off = 4; off; off >>= 1)
            m = fmaxf(m, __shfl_xor_sync(0xFFFFFFFFu, m, off));
        if (lane == 0) red[0] = m;
    }
    __syncthreads();
    mx = red[0];
    __syncthreads();

    float4 e;
    e.x = __expf(v.x - mx); e.y = __expf(v.y - mx);
    e.z = __expf(v.z - mx); e.w = __expf(v.w - mx);
    float sum = e.x + e.y + e.z + e.w;
    #pragma unroll
    for (int off = 16; off; off >>= 1)
        sum += __shfl_xor_sync(0xFFFFFFFFu, sum, off);
    if (lane == 0) red[warp] = sum;
    __syncthreads();
    if (warp == 0) {
        float s = red[lane & 7];
        #pragma unroll
        for (int off = 4; off; off >>= 1)
            s += __shfl_xor_sync(0xFFFFFFFFu, s, off);
        if (lane == 0) red[0] = s;
    }
    __syncthreads();
    const float inv = 1.0f / red[0];

    e.x *= inv; e.y *= inv; e.z *= inv; e.w *= inv;
    *(float4*)rp = e;
}

// -------------------------------------------------------------------------
// AV GEMM, split-K=16, SINGLE-SHOT: the whole 64-k chunk is loaded in one
// burst (6 independent LDG.128/thread, MLP=6, one L2 round trip), one
// __syncthreads, then a straight 64-deep FMA loop with no further barriers.
// Accumulation order over k identical to the staged version.
// Tile: 32 rows x 64 vdims. Grid: (4, 16, 16) = 1024 blocks.
// -------------------------------------------------------------------------
__global__ __launch_bounds__(256) void av_kernel(
    const float* __restrict__ V, const int* __restrict__ valid_lens,
    float* __restrict__ out)
{
    __shared__ float Ps[32][65];    // [row][k]  8.3 KB
    __shared__ float Vs[64][68];    // [k][v]   17.4 KB

    const int v0 = blockIdx.x * 64;
    const int r0 = blockIdx.y * 32;          // global row (b*NQ + q)
    const int b  = r0 >> 7;
    const int kz = blockIdx.z * 64;

    if (kz >= valid_lens[b]) return;         // probs exactly zero here

    const int tid = threadIdx.x;
    const int tx = tid & 15;
    const int ty = tid >> 4;                 // 0..15

    const int vlr = tid >> 4;                // 0..15
    const int vlc = (tid & 15) * 4;          // 0..60

    const float* Vb = V + (size_t)b * NK * DV;

    // ---- burst load: all 6 LDG.128 issued before any STS (MLP = 6) ----
    float4 pbuf[2], vbuf[4];
    #pragma unroll
    for (int u = 0; u < 2; u++) {
        const int fi = tid * 2 + u;          // 0..511 float4s of P chunk
        const int pr = fi >> 4;              // 0..31
        const int pc = (fi & 15) * 4;        // 0..60
        pbuf[u] = *(const float4*)&g_scores[(size_t)(r0 + pr) * NK + kz + pc];
    }
    #pragma unroll
    for (int u = 0; u < 4; u++) {
        const int kr = u * 16 + vlr;         // 0..63
        vbuf[u] = *(const float4*)&Vb[(size_t)(kz + kr) * DV + v0 + vlc];
    }

    #pragma unroll
    for (int u = 0; u < 2; u++) {
        const int fi = tid * 2 + u;
        const int pr = fi >> 4;
        const int pc = (fi & 15) * 4;
        Ps[pr][pc + 0] = pbuf[u].x; Ps[pr][pc + 1] = pbuf[u].y;
        Ps[pr][pc + 2] = pbuf[u].z; Ps[pr][pc + 3] = pbuf[u].w;
    }
    #pragma unroll
    for (int u = 0; u < 4; u++) {
        const int kr = u * 16 + vlr;
        Vs[kr][vlc + 0] = vbuf[u].x; Vs[kr][vlc + 1] = vbuf[u].y;
        Vs[kr][vlc + 2] = vbuf[u].z; Vs[kr][vlc + 3] = vbuf[u].w;
    }
    __syncthreads();

    // ---- one straight 64-deep MAC loop, no further barriers ----
    float acc[2][4] = {};
    #pragma unroll 8
    for (int dd = 0; dd < 64; dd++) {
        const float p0 = Ps[ty * 2 + 0][dd];
        const float p1 = Ps[ty * 2 + 1][dd];
        const float4 vr = *(const float4*)&Vs[dd][tx * 4];
        acc[0][0] += p0 * vr.x; acc[0][1] += p0 * vr.y;
        acc[0][2] += p0 * vr.z; acc[0][3] += p0 * vr.w;
        acc[1][0] += p1 * vr.x; acc[1][1] += p1 * vr.y;
        acc[1][2] += p1 * vr.z; acc[1][3] += p1 * vr.w;
    }

    #pragma unroll
    for (int i = 0; i < 2; i++)
        #pragma unroll
        for (int j = 0; j < 4; j++)
            atomicAdd(&out[(size_t)(r0 + ty * 2 + i) * DV + v0 + tx * 4 + j],
                      acc[i][j]);
}

// -------------------------------------------------------------------------
extern "C" void kernel_launch(void* const* d_in, const int* in_sizes, int n_in,
                              void* d_out, int out_size)
{
    const float* queries = (const float*)d_in[0];
    const float* keys    = (const float*)d_in[1];
    const float* values  = (const float*)d_in[2];
    const int*   vlens   = (const int*)d_in[3];
    const float* Wq      = (const float*)d_in[4];
    const float* Wk      = (const float*)d_in[5];
    const float* wv      = (const float*)d_in[6];
    float* out = (float*)d_out;

    // fused q+k projection on tensor cores (3xTF32); dead k tiles skipped
    proj_kernel<<<dim3(4, 72), 256>>>(queries, keys, Wq, Wk, vlens);
    // scores (f32 tanh, only k < valid_len)
    scores_kernel<<<dim3(16, 16, 4), 128>>>(wv, vlens);
    // masked softmax (in place) + zero output rows
    softmax_kernel<<<512, 256>>>(vlens, out);
    // AV GEMM, split-K=16, single-shot burst load
    av_kernel<<<dim3(4, 16, 16), 256>>>(values, vlens, out);
}